// round 1
// baseline (speedup 1.0000x reference)
#include <cuda_runtime.h>
#include <math.h>

#define BB   2
#define SS   2048
#define HH   16
#define DK   64
#define DM   1024
#define TOK  (BB*SS)   // 4096

// Scratch (allocation-free rule: __device__ globals)
__device__ float g_q[(size_t)BB*HH*SS*DK];     // 16 MB, [B,H,S,dk]
__device__ float g_k[(size_t)BB*HH*SS*DK];
__device__ float g_v[(size_t)BB*HH*SS*DK];
__device__ float g_p[(size_t)BB*HH*SS*SS];     // 512 MB scores/probs
__device__ float g_ctx[(size_t)TOK*DM];        // 16 MB, [B,S,D]

// ---------------------------------------------------------------------------
// Generic C = alpha * A @ B^T (+bias). A:[M,K] rm, B:[N,K] rm.
// MODE 0: C row-major [M,N] (+batch offset)
// MODE 1: projection epilogue -> [B,H,S,dk] layout (row=token, col=h*64+d)
// 128x128 tile, BK=8, 256 threads, 8x8 per-thread microtile.
// Requires M,N multiples of 128 and K multiple of 8 (true for all uses).
// ---------------------------------------------------------------------------
template<int MODE>
__global__ __launch_bounds__(256) void sgemm_tn(
    const float* __restrict__ A, const float* __restrict__ Bm,
    const float* __restrict__ bias, float* __restrict__ C,
    int M, int N, int K, size_t aB, size_t bB, size_t cB, float alpha)
{
    A  += (size_t)blockIdx.z * aB;
    Bm += (size_t)blockIdx.z * bB;
    C  += (size_t)blockIdx.z * cB;

    __shared__ float As[8][128];
    __shared__ float Bs[8][128];

    const int t  = threadIdx.x;
    const int tx = t & 15;        // 0..15 -> 8 cols each
    const int ty = t >> 4;        // 0..15 -> 8 rows each
    const int bm = blockIdx.y * 128;
    const int bn = blockIdx.x * 128;

    const int lr = t >> 1;        // 0..127 load row
    const int lc = (t & 1) * 4;   // 0 or 4 load col

    const float* Ag = A  + (size_t)(bm + lr) * K + lc;
    const float* Bg = Bm + (size_t)(bn + lr) * K + lc;

    float acc[8][8];
#pragma unroll
    for (int i = 0; i < 8; i++)
#pragma unroll
        for (int j = 0; j < 8; j++) acc[i][j] = 0.f;

    for (int k0 = 0; k0 < K; k0 += 8) {
        float4 av = *(const float4*)(Ag + k0);
        float4 bv = *(const float4*)(Bg + k0);
        __syncthreads();
        As[lc+0][lr] = av.x; As[lc+1][lr] = av.y; As[lc+2][lr] = av.z; As[lc+3][lr] = av.w;
        Bs[lc+0][lr] = bv.x; Bs[lc+1][lr] = bv.y; Bs[lc+2][lr] = bv.z; Bs[lc+3][lr] = bv.w;
        __syncthreads();
#pragma unroll
        for (int k = 0; k < 8; k++) {
            float a[8], b[8];
            *(float4*)&a[0] = *(const float4*)&As[k][ty*8];
            *(float4*)&a[4] = *(const float4*)&As[k][ty*8 + 4];
            *(float4*)&b[0] = *(const float4*)&Bs[k][tx*8];
            *(float4*)&b[4] = *(const float4*)&Bs[k][tx*8 + 4];
#pragma unroll
            for (int i = 0; i < 8; i++)
#pragma unroll
                for (int j = 0; j < 8; j++)
                    acc[i][j] = fmaf(a[i], b[j], acc[i][j]);
        }
    }

#pragma unroll
    for (int i = 0; i < 8; i++) {
        const int row = bm + ty*8 + i;
#pragma unroll
        for (int j = 0; j < 8; j += 4) {
            const int col = bn + tx*8 + j;
            float4 v;
            v.x = alpha * acc[i][j+0] + (bias ? bias[col+0] : 0.f);
            v.y = alpha * acc[i][j+1] + (bias ? bias[col+1] : 0.f);
            v.z = alpha * acc[i][j+2] + (bias ? bias[col+2] : 0.f);
            v.w = alpha * acc[i][j+3] + (bias ? bias[col+3] : 0.f);
            if (MODE == 0) {
                *(float4*)(C + (size_t)row * N + col) = v;
            } else {
                const int b_ = row >> 11, s_ = row & 2047;
                const int h_ = col >> 6,  d_ = col & 63;
                *(float4*)(C + ((size_t)((b_*HH + h_)*SS + s_)) * DK + d_) = v;
            }
        }
    }
}

// ---------------------------------------------------------------------------
// In-place row softmax over [rows, 2048]. One block (256 thr) per row.
// ---------------------------------------------------------------------------
__global__ __launch_bounds__(256) void softmax_rows(float* __restrict__ P)
{
    float4* row = (float4*)(P + (size_t)blockIdx.x * SS);
    const int t = threadIdx.x;
    float4 a = row[t];
    float4 b = row[t + 256];

    __shared__ float red[8];

    float m = fmaxf(fmaxf(fmaxf(a.x, a.y), fmaxf(a.z, a.w)),
                    fmaxf(fmaxf(b.x, b.y), fmaxf(b.z, b.w)));
#pragma unroll
    for (int o = 16; o > 0; o >>= 1) m = fmaxf(m, __shfl_xor_sync(0xffffffffu, m, o));
    if ((t & 31) == 0) red[t >> 5] = m;
    __syncthreads();
    if (t < 32) {
        float x = (t < 8) ? red[t] : -1e30f;
#pragma unroll
        for (int o = 4; o > 0; o >>= 1) x = fmaxf(x, __shfl_xor_sync(0xffffffffu, x, o));
        if (t == 0) red[0] = x;
    }
    __syncthreads();
    m = red[0];

    a.x = __expf(a.x - m); a.y = __expf(a.y - m); a.z = __expf(a.z - m); a.w = __expf(a.w - m);
    b.x = __expf(b.x - m); b.y = __expf(b.y - m); b.z = __expf(b.z - m); b.w = __expf(b.w - m);
    float s = (a.x + a.y + a.z + a.w) + (b.x + b.y + b.z + b.w);
#pragma unroll
    for (int o = 16; o > 0; o >>= 1) s += __shfl_xor_sync(0xffffffffu, s, o);
    __syncthreads();                       // everyone has read red[0]
    if ((t & 31) == 0) red[t >> 5] = s;
    __syncthreads();
    if (t < 32) {
        float x = (t < 8) ? red[t] : 0.f;
#pragma unroll
        for (int o = 4; o > 0; o >>= 1) x += __shfl_xor_sync(0xffffffffu, x, o);
        if (t == 0) red[0] = x;
    }
    __syncthreads();
    const float inv = 1.0f / red[0];

    a.x *= inv; a.y *= inv; a.z *= inv; a.w *= inv;
    b.x *= inv; b.y *= inv; b.z *= inv; b.w *= inv;
    row[t] = a;
    row[t + 256] = b;
}

// ---------------------------------------------------------------------------
// ctx[b,s, h*64+d] = sum_j P[bh,s,j] * v[bh,j,d]
// Per (bh): [2048,2048] @ [2048,64]. Tile 128x64, BK=16, 256 threads, 8x4/thr.
// ---------------------------------------------------------------------------
__global__ __launch_bounds__(256) void pv_kernel(
    const float* __restrict__ P, const float* __restrict__ V,
    float* __restrict__ ctx)
{
    const int z = blockIdx.z;  // bh
    const float* Pb = P + (size_t)z * SS * SS + (size_t)blockIdx.x * 128 * SS;
    const float* Vb = V + (size_t)z * SS * DK;

    __shared__ float Ps[16][128];
    __shared__ float Vs[16][64];

    const int t  = threadIdx.x;
    const int tx = t & 15;     // 4 cols each
    const int ty = t >> 4;     // 8 rows each
    const int pr = t >> 2;     // 0..63
    const int pc = (t & 3) * 4;
    const int vr = t >> 4;     // 0..15
    const int vc = (t & 15) * 4;

    float acc[8][4];
#pragma unroll
    for (int i = 0; i < 8; i++)
#pragma unroll
        for (int j = 0; j < 4; j++) acc[i][j] = 0.f;

    for (int k0 = 0; k0 < SS; k0 += 16) {
        float4 p0 = *(const float4*)(Pb + (size_t)pr        * SS + k0 + pc);
        float4 p1 = *(const float4*)(Pb + (size_t)(pr + 64) * SS + k0 + pc);
        float4 vv = *(const float4*)(Vb + (size_t)(k0 + vr) * DK + vc);
        __syncthreads();
        Ps[pc+0][pr]    = p0.x; Ps[pc+1][pr]    = p0.y; Ps[pc+2][pr]    = p0.z; Ps[pc+3][pr]    = p0.w;
        Ps[pc+0][pr+64] = p1.x; Ps[pc+1][pr+64] = p1.y; Ps[pc+2][pr+64] = p1.z; Ps[pc+3][pr+64] = p1.w;
        *(float4*)&Vs[vr][vc] = vv;
        __syncthreads();
#pragma unroll
        for (int k = 0; k < 16; k++) {
            float a[8], b[4];
            *(float4*)&a[0] = *(const float4*)&Ps[k][ty*8];
            *(float4*)&a[4] = *(const float4*)&Ps[k][ty*8 + 4];
            *(float4*)&b[0] = *(const float4*)&Vs[k][tx*4];
#pragma unroll
            for (int i = 0; i < 8; i++)
#pragma unroll
                for (int j = 0; j < 4; j++)
                    acc[i][j] = fmaf(a[i], b[j], acc[i][j]);
        }
    }

    const int b_ = z >> 4, h_ = z & 15;
#pragma unroll
    for (int i = 0; i < 8; i++) {
        const int s_ = blockIdx.x * 128 + ty*8 + i;
        float4 v = make_float4(acc[i][0], acc[i][1], acc[i][2], acc[i][3]);
        *(float4*)(ctx + ((size_t)(b_*SS + s_)) * DM + h_*DK + tx*4) = v;
    }
}

// ---------------------------------------------------------------------------
extern "C" void kernel_launch(void* const* d_in, const int* in_sizes, int n_in,
                              void* d_out, int out_size)
{
    const float* Q  = (const float*)d_in[0];
    const float* Kx = (const float*)d_in[1];
    const float* Vx = (const float*)d_in[2];
    const float* Wq = (const float*)d_in[3];
    const float* bq = (const float*)d_in[4];
    const float* Wk = (const float*)d_in[5];
    const float* bk = (const float*)d_in[6];
    const float* Wv = (const float*)d_in[7];
    const float* bv = (const float*)d_in[8];
    const float* Wo = (const float*)d_in[9];
    const float* bo = (const float*)d_in[10];
    float* out = (float*)d_out;

    float *gq, *gk, *gv, *gp, *gc;
    cudaGetSymbolAddress((void**)&gq, g_q);
    cudaGetSymbolAddress((void**)&gk, g_k);
    cudaGetSymbolAddress((void**)&gv, g_v);
    cudaGetSymbolAddress((void**)&gp, g_p);
    cudaGetSymbolAddress((void**)&gc, g_ctx);

    dim3 blk(256);

    // 1) Q/K/V projections: [4096,1024] @ [1024,1024]^T + bias -> [B,H,S,dk]
    dim3 gproj(DM / 128, TOK / 128, 1);   // (8, 32)
    sgemm_tn<1><<<gproj, blk>>>(Q,  Wq, bq, gq, TOK, DM, DM, 0, 0, 0, 1.0f);
    sgemm_tn<1><<<gproj, blk>>>(Kx, Wk, bk, gk, TOK, DM, DM, 0, 0, 0, 1.0f);
    sgemm_tn<1><<<gproj, blk>>>(Vx, Wv, bv, gv, TOK, DM, DM, 0, 0, 0, 1.0f);

    // 2) scores = (q @ k^T) / 8 per (b,h)
    dim3 gsc(SS / 128, SS / 128, BB * HH); // (16,16,32)
    sgemm_tn<0><<<gsc, blk>>>(gq, gk, nullptr, gp, SS, SS, DK,
                              (size_t)SS * DK, (size_t)SS * DK,
                              (size_t)SS * SS, 0.125f);

    // 3) softmax in place over rows
    softmax_rows<<<BB * HH * SS, blk>>>(gp);

    // 4) ctx = P @ v  -> [B,S,D]
    dim3 gpv(SS / 128, 1, BB * HH);       // (16,1,32)
    pv_kernel<<<gpv, blk>>>(gp, gv, gc);

    // 5) out = ctx @ Wo^T + bo
    dim3 gout(DM / 128, TOK / 128, 1);
    sgemm_tn<0><<<gout, blk>>>(gc, Wo, bo, out, TOK, DM, DM, 0, 0, 0, 1.0f);
}

// round 2
// speedup vs baseline: 3.0676x; 3.0676x over previous
#include <cuda_runtime.h>
#include <math.h>

#define BB   2
#define SS   2048
#define HH   16
#define DK   64
#define DM   1024
#define TOK  (BB*SS)   // 4096
#define BH   (BB*HH)   // 32

// Scratch (allocation-free rule: __device__ globals)
__device__ float g_q[(size_t)BH*SS*DK];     // 16 MB, [bh, s, dk]
__device__ float g_k[(size_t)BH*SS*DK];
__device__ float g_v[(size_t)BH*SS*DK];
__device__ float g_ctx[(size_t)TOK*DM];     // 16 MB, [B,S,D]

// ---------------------------------------------------------------------------
// helpers
// ---------------------------------------------------------------------------
__device__ __forceinline__ unsigned f2tf(float x) {
    unsigned r;
    asm("cvt.rna.tf32.f32 %0, %1;" : "=r"(r) : "f"(x));
    return r;
}

__device__ __forceinline__ void mma_tf32(float c[4], const unsigned a[4],
                                         unsigned b0, unsigned b1) {
    asm volatile(
        "mma.sync.aligned.m16n8k8.row.col.f32.tf32.tf32.f32 "
        "{%0,%1,%2,%3}, {%4,%5,%6,%7}, {%8,%9}, {%0,%1,%2,%3};"
        : "+f"(c[0]), "+f"(c[1]), "+f"(c[2]), "+f"(c[3])
        : "r"(a[0]), "r"(a[1]), "r"(a[2]), "r"(a[3]), "r"(b0), "r"(b1));
}

// ---------------------------------------------------------------------------
// C = A @ B^T (+bias). A:[M,K] rm, B:[N,K] rm. tf32 tensor cores.
// MODE 0: C row-major [M,N].  MODE 1: scatter to [bh, s, dk] head layout.
// 128x128 tile, BK=32, 256 threads (8 warps, 4x2 warp grid, 32x64 per warp).
// M,N multiples of 128; K multiple of 32.
// ---------------------------------------------------------------------------
template<int MODE>
__global__ __launch_bounds__(256) void gemm_tf32(
    const float* __restrict__ A, const float* __restrict__ Bm,
    const float* __restrict__ bias, float* __restrict__ C,
    int M, int N, int K)
{
    __shared__ unsigned As[128][36];
    __shared__ unsigned Bs[128][36];

    const int t    = threadIdx.x;
    const int lane = t & 31, wid = t >> 5;
    const int g    = lane >> 2, tig = lane & 3;
    const int wm   = (wid & 3) * 32;
    const int wn   = (wid >> 2) * 64;
    const int bm   = blockIdx.y * 128;
    const int bn   = blockIdx.x * 128;

    const int lrow = t >> 1;
    const int lcol = (t & 1) * 16;

    float acc[2][8][4];
#pragma unroll
    for (int mi = 0; mi < 2; mi++)
#pragma unroll
        for (int nj = 0; nj < 8; nj++)
#pragma unroll
            for (int x = 0; x < 4; x++) acc[mi][nj][x] = 0.f;

    const float* Ag = A  + (size_t)(bm + lrow) * K + lcol;
    const float* Bg = Bm + (size_t)(bn + lrow) * K + lcol;

    for (int k0 = 0; k0 < K; k0 += 32) {
        uint4 av[4], bv[4];
#pragma unroll
        for (int i = 0; i < 4; i++) {
            float4 a = *(const float4*)(Ag + k0 + i * 4);
            float4 b = *(const float4*)(Bg + k0 + i * 4);
            av[i] = make_uint4(f2tf(a.x), f2tf(a.y), f2tf(a.z), f2tf(a.w));
            bv[i] = make_uint4(f2tf(b.x), f2tf(b.y), f2tf(b.z), f2tf(b.w));
        }
        __syncthreads();
#pragma unroll
        for (int i = 0; i < 4; i++) {
            *(uint4*)&As[lrow][lcol + i * 4] = av[i];
            *(uint4*)&Bs[lrow][lcol + i * 4] = bv[i];
        }
        __syncthreads();

#pragma unroll
        for (int k8 = 0; k8 < 4; k8++) {
            const int kk = k8 * 8;
            unsigned a[2][4], b[8][2];
#pragma unroll
            for (int mi = 0; mi < 2; mi++) {
                const int r = wm + mi * 16;
                a[mi][0] = As[r + g    ][kk + tig];
                a[mi][1] = As[r + g + 8][kk + tig];
                a[mi][2] = As[r + g    ][kk + tig + 4];
                a[mi][3] = As[r + g + 8][kk + tig + 4];
            }
#pragma unroll
            for (int nj = 0; nj < 8; nj++) {
                const int r = wn + nj * 8 + g;
                b[nj][0] = Bs[r][kk + tig];
                b[nj][1] = Bs[r][kk + tig + 4];
            }
#pragma unroll
            for (int mi = 0; mi < 2; mi++)
#pragma unroll
                for (int nj = 0; nj < 8; nj++)
                    mma_tf32(acc[mi][nj], a[mi], b[nj][0], b[nj][1]);
        }
    }

#pragma unroll
    for (int mi = 0; mi < 2; mi++) {
#pragma unroll
        for (int nj = 0; nj < 8; nj++) {
            const int col = bn + wn + nj * 8 + 2 * tig;
            const float bx = bias ? bias[col]     : 0.f;
            const float by = bias ? bias[col + 1] : 0.f;
            const int r0 = bm + wm + mi * 16 + g;
            const int r1 = r0 + 8;
            float2 v0 = make_float2(acc[mi][nj][0] + bx, acc[mi][nj][1] + by);
            float2 v1 = make_float2(acc[mi][nj][2] + bx, acc[mi][nj][3] + by);
            if (MODE == 0) {
                *(float2*)(C + (size_t)r0 * N + col) = v0;
                *(float2*)(C + (size_t)r1 * N + col) = v1;
            } else {
                const int h_ = col >> 6, d_ = col & 63;
                {
                    const int b_ = r0 >> 11, s_ = r0 & 2047;
                    *(float2*)(C + ((size_t)((b_*HH + h_)*SS + s_))*DK + d_) = v0;
                }
                {
                    const int b_ = r1 >> 11, s_ = r1 & 2047;
                    *(float2*)(C + ((size_t)((b_*HH + h_)*SS + s_))*DK + d_) = v1;
                }
            }
        }
    }
}

// ---------------------------------------------------------------------------
// Fused flash attention. grid=(S/128, BH), 256 threads (8 warps).
// Each warp owns 16 q rows; kv tiles of 64. tf32 mma for QK^T and P@V,
// fp32 online softmax. Q scaled by 1/8 at load. Output -> ctx [B,S,DM].
// ---------------------------------------------------------------------------
__global__ __launch_bounds__(256) void flash_attn(
    const float* __restrict__ q, const float* __restrict__ k,
    const float* __restrict__ v, float* __restrict__ ctx)
{
    extern __shared__ unsigned sm[];
    unsigned (*Ks)[68] = (unsigned(*)[68])sm;               // 64x68
    unsigned (*Vs)[72] = (unsigned(*)[72])(sm + 64 * 68);   // 64x72
    unsigned* Ps = sm + 64 * 68 + 64 * 72;                  // 8 warps x 16 x 68

    const int t    = threadIdx.x;
    const int lane = t & 31, wid = t >> 5;
    const int g    = lane >> 2, tig = lane & 3;
    const int bh   = blockIdx.y;
    const int q0   = blockIdx.x * 128;

    // Q fragments in registers, pre-scaled by 1/sqrt(dk)=0.125
    const float* qb = q + ((size_t)bh * SS + q0 + wid * 16) * DK;
    unsigned aq[8][4];
#pragma unroll
    for (int k8 = 0; k8 < 8; k8++) {
        aq[k8][0] = f2tf(qb[(size_t)g       * DK + k8*8 + tig    ] * 0.125f);
        aq[k8][1] = f2tf(qb[(size_t)(g + 8) * DK + k8*8 + tig    ] * 0.125f);
        aq[k8][2] = f2tf(qb[(size_t)g       * DK + k8*8 + tig + 4] * 0.125f);
        aq[k8][3] = f2tf(qb[(size_t)(g + 8) * DK + k8*8 + tig + 4] * 0.125f);
    }

    float o[8][4];
#pragma unroll
    for (int nj = 0; nj < 8; nj++)
#pragma unroll
        for (int x = 0; x < 4; x++) o[nj][x] = 0.f;
    float mrun0 = -1e30f, mrun1 = -1e30f, l0 = 0.f, l1 = 0.f;

    const int lr  = t >> 2;        // 0..63 tile row
    const int lc4 = t & 3;
    const float* kb = k + (size_t)bh * SS * DK;
    const float* vb = v + (size_t)bh * SS * DK;
    unsigned* PsW = Ps + wid * 16 * 68;

    for (int kt = 0; kt < SS / 64; kt++) {
        __syncthreads();
#pragma unroll
        for (int i = 0; i < 4; i++) {
            const int c = (lc4 + i * 4) * 4;
            float4 kk4 = *(const float4*)(kb + (size_t)(kt*64 + lr) * DK + c);
            float4 vv4 = *(const float4*)(vb + (size_t)(kt*64 + lr) * DK + c);
            *(uint4*)&Ks[lr][c] = make_uint4(f2tf(kk4.x), f2tf(kk4.y), f2tf(kk4.z), f2tf(kk4.w));
            *(uint4*)&Vs[lr][c] = make_uint4(f2tf(vv4.x), f2tf(vv4.y), f2tf(vv4.z), f2tf(vv4.w));
        }
        __syncthreads();

        // S = Q @ K^T
        float sacc[8][4];
#pragma unroll
        for (int nj = 0; nj < 8; nj++)
#pragma unroll
            for (int x = 0; x < 4; x++) sacc[nj][x] = 0.f;
#pragma unroll
        for (int k8 = 0; k8 < 8; k8++) {
#pragma unroll
            for (int nj = 0; nj < 8; nj++) {
                unsigned b0 = Ks[nj*8 + g][k8*8 + tig];
                unsigned b1 = Ks[nj*8 + g][k8*8 + tig + 4];
                mma_tf32(sacc[nj], aq[k8], b0, b1);
            }
        }

        // online softmax (rows g and g+8 of this warp's 16)
        float mx0 = -1e30f, mx1 = -1e30f;
#pragma unroll
        for (int nj = 0; nj < 8; nj++) {
            mx0 = fmaxf(mx0, fmaxf(sacc[nj][0], sacc[nj][1]));
            mx1 = fmaxf(mx1, fmaxf(sacc[nj][2], sacc[nj][3]));
        }
        mx0 = fmaxf(mx0, __shfl_xor_sync(0xffffffffu, mx0, 1));
        mx0 = fmaxf(mx0, __shfl_xor_sync(0xffffffffu, mx0, 2));
        mx1 = fmaxf(mx1, __shfl_xor_sync(0xffffffffu, mx1, 1));
        mx1 = fmaxf(mx1, __shfl_xor_sync(0xffffffffu, mx1, 2));

        const float mn0 = fmaxf(mrun0, mx0), mn1 = fmaxf(mrun1, mx1);
        const float al0 = __expf(mrun0 - mn0), al1 = __expf(mrun1 - mn1);
        float s0 = 0.f, s1 = 0.f;
#pragma unroll
        for (int nj = 0; nj < 8; nj++) {
            float p0 = __expf(sacc[nj][0] - mn0);
            float p1 = __expf(sacc[nj][1] - mn0);
            float p2 = __expf(sacc[nj][2] - mn1);
            float p3 = __expf(sacc[nj][3] - mn1);
            s0 += p0 + p1; s1 += p2 + p3;
            unsigned* pr0 = PsW + (size_t)g * 68 + nj*8 + 2*tig;
            unsigned* pr1 = PsW + (size_t)(g + 8) * 68 + nj*8 + 2*tig;
            pr0[0] = f2tf(p0); pr0[1] = f2tf(p1);
            pr1[0] = f2tf(p2); pr1[1] = f2tf(p3);
            o[nj][0] *= al0; o[nj][1] *= al0;
            o[nj][2] *= al1; o[nj][3] *= al1;
        }
        s0 += __shfl_xor_sync(0xffffffffu, s0, 1);
        s0 += __shfl_xor_sync(0xffffffffu, s0, 2);
        s1 += __shfl_xor_sync(0xffffffffu, s1, 1);
        s1 += __shfl_xor_sync(0xffffffffu, s1, 2);
        l0 = l0 * al0 + s0;
        l1 = l1 * al1 + s1;
        mrun0 = mn0; mrun1 = mn1;
        __syncwarp();

        // O += P @ V
#pragma unroll
        for (int k8 = 0; k8 < 8; k8++) {
            unsigned ap[4];
            ap[0] = PsW[(size_t)g       * 68 + k8*8 + tig];
            ap[1] = PsW[(size_t)(g + 8) * 68 + k8*8 + tig];
            ap[2] = PsW[(size_t)g       * 68 + k8*8 + tig + 4];
            ap[3] = PsW[(size_t)(g + 8) * 68 + k8*8 + tig + 4];
#pragma unroll
            for (int nj = 0; nj < 8; nj++) {
                unsigned b0 = Vs[k8*8 + tig    ][nj*8 + g];
                unsigned b1 = Vs[k8*8 + tig + 4][nj*8 + g];
                mma_tf32(o[nj], ap, b0, b1);
            }
        }
    }

    // write ctx [B,S,DM] at head column offset
    const float inv0 = 1.f / l0, inv1 = 1.f / l1;
    const int b_ = bh >> 4, h_ = bh & 15;
    const int r0 = q0 + wid * 16 + g;
    float* cb = ctx + (size_t)b_ * SS * DM + (size_t)h_ * DK;
#pragma unroll
    for (int nj = 0; nj < 8; nj++) {
        const int col = nj * 8 + 2 * tig;
        *(float2*)(cb + (size_t)r0       * DM + col) =
            make_float2(o[nj][0] * inv0, o[nj][1] * inv0);
        *(float2*)(cb + (size_t)(r0 + 8) * DM + col) =
            make_float2(o[nj][2] * inv1, o[nj][3] * inv1);
    }
}

// ---------------------------------------------------------------------------
extern "C" void kernel_launch(void* const* d_in, const int* in_sizes, int n_in,
                              void* d_out, int out_size)
{
    const float* Q  = (const float*)d_in[0];
    const float* Kx = (const float*)d_in[1];
    const float* Vx = (const float*)d_in[2];
    const float* Wq = (const float*)d_in[3];
    const float* bq = (const float*)d_in[4];
    const float* Wk = (const float*)d_in[5];
    const float* bk = (const float*)d_in[6];
    const float* Wv = (const float*)d_in[7];
    const float* bv = (const float*)d_in[8];
    const float* Wo = (const float*)d_in[9];
    const float* bo = (const float*)d_in[10];
    float* out = (float*)d_out;

    float *gq, *gk, *gv, *gc;
    cudaGetSymbolAddress((void**)&gq, g_q);
    cudaGetSymbolAddress((void**)&gk, g_k);
    cudaGetSymbolAddress((void**)&gv, g_v);
    cudaGetSymbolAddress((void**)&gc, g_ctx);

    static bool attr_set = false;
    if (!attr_set) {
        cudaFuncSetAttribute(flash_attn,
                             cudaFuncAttributeMaxDynamicSharedMemorySize, 70656);
        attr_set = true;
    }

    dim3 blk(256);

    // 1) projections -> [bh, s, dk]
    dim3 gproj(DM / 128, TOK / 128);
    gemm_tf32<1><<<gproj, blk>>>(Q,  Wq, bq, gq, TOK, DM, DM);
    gemm_tf32<1><<<gproj, blk>>>(Kx, Wk, bk, gk, TOK, DM, DM);
    gemm_tf32<1><<<gproj, blk>>>(Vx, Wv, bv, gv, TOK, DM, DM);

    // 2) fused attention -> ctx [B,S,DM]
    dim3 gfa(SS / 128, BH);
    flash_attn<<<gfa, blk, 70656>>>(gq, gk, gv, gc);

    // 3) out = ctx @ Wo^T + bo
    dim3 gout(DM / 128, TOK / 128);
    gemm_tf32<0><<<gout, blk>>>(gc, Wo, bo, out, TOK, DM, DM);
}